// round 12
// baseline (speedup 1.0000x reference)
#include <cuda_runtime.h>
#include <cuda_fp16.h>

// CNNEmbedding via vocab-factorized fp16 table, split-filter-bank edition.
// R12: build_table stages the FULL weight set (160KB) in dynamic smem via one
// coalesced pass, then computes from conflict-free LDS. cnn_max identical to
// R10 (best measured: 24.8us).

#define VOC 512
#define EMB 128
#define NF 16
#define NPAIR 20
#define LSEQ 32
#define VT 4
#define NW (NF * NPAIR)       // 320
#define W_FLOATS (EMB * NW)   // 40960 floats = 160KB
#define ROW_HALVES 512        // per-v: 2 groups x 2 chunks x 16 f x 8 halves

__device__ __align__(16) __half g_Th[(VOC + 1) * ROW_HALVES];   // zero-init; row VOC = unk

// ---------------------------------------------------------------------------
// Kernel 1: build table. grid = VOC/VT = 128, block = 320 (16 f x 20 taps).
// Dynamic smem: sw[40960] (weights transposed [e][f*20+pr]) + se[512] (emb [e][t]).
// ---------------------------------------------------------------------------
__global__ void __launch_bounds__(320) build_table(
    const float* __restrict__ emb,
    const float* __restrict__ w2, const float* __restrict__ w3,
    const float* __restrict__ w4, const float* __restrict__ w5,
    const float* __restrict__ w6)
{
    extern __shared__ __align__(16) float smem[];
    float* sw = smem;                 // 40960 floats
    float* se = smem + W_FLOATS;      // 512 floats, [e][t]

    const int v0  = blockIdx.x * VT;
    const int tid = threadIdx.x;

    // Stage emb transposed: [e][t]
    for (int i = tid; i < VT * EMB; i += 320) {
        const int t = i >> 7;
        const int e = i & 127;
        se[e * VT + t] = emb[v0 * EMB + i];
    }

    // Stage all weights, coalesced float4 reads, scattered smem writes.
    // Array ki: layout [16, 128, k]; element idx -> (f, e, j);
    // smem slot = e*320 + f*20 + TB[ki] + j.
    {
        const float* WS[5] = {w2, w3, w4, w5, w6};
        const int KS[5] = {2, 3, 4, 5, 6};
        const int TB[5] = {0, 2, 5, 9, 14};
#pragma unroll
        for (int ki = 0; ki < 5; ++ki) {
            const int k = KS[ki], tb = TB[ki];
            const int tot4 = (NF * EMB * k) >> 2;      // float4 count
            const float4* w4p = reinterpret_cast<const float4*>(WS[ki]);
            for (int i4 = tid; i4 < tot4; i4 += 320) {
                const float4 val = w4p[i4];
                const int base = i4 << 2;
                const int f = base / (EMB * k);        // same f for all 4 elems
                const int r0 = base - f * EMB * k;
#pragma unroll
                for (int u = 0; u < 4; ++u) {
                    const int r = r0 + u;
                    const int e = r / k;
                    const int j = r - e * k;
                    sw[e * NW + f * NPAIR + tb + j] =
                        (u == 0) ? val.x : (u == 1) ? val.y : (u == 2) ? val.z : val.w;
                }
            }
        }
    }
    __syncthreads();

    float acc[VT];
#pragma unroll
    for (int t = 0; t < VT; ++t) acc[t] = 0.f;

#pragma unroll 4
    for (int e = 0; e < EMB; ++e) {
        const float we = sw[e * NW + tid];                         // conflict-free LDS
        const float4 ev = *reinterpret_cast<const float4*>(&se[e * VT]);  // broadcast
        acc[0] = fmaf(ev.x, we, acc[0]);
        acc[1] = fmaf(ev.y, we, acc[1]);
        acc[2] = fmaf(ev.z, we, acc[2]);
        acc[3] = fmaf(ev.w, we, acc[3]);
    }

    // Store to split layout: group g = (pr >= 9), slot = pr - 9*g,
    // chunk c = slot/8, half h = slot%8.
    const int f  = tid / NPAIR;
    const int pr = tid - f * NPAIR;
    const int g = (pr >= 9) ? 1 : 0;
    const int slot = pr - 9 * g;
    const int c = slot >> 3;
    const int h = slot & 7;
    const int off = g * 256 + c * 128 + f * 8 + h;
#pragma unroll
    for (int t = 0; t < VT; ++t)
        g_Th[(v0 + t) * ROW_HALVES + off] = __float2half(acc[t]);
}

// ---------------------------------------------------------------------------
// Kernel 2: gather + fp16 dual-word sliding-window max (identical to R10).
// block = 512 = [g:2][wordpair:16][f:16]; grid = 512 (32 words per block).
// ---------------------------------------------------------------------------
__device__ __forceinline__ void pack2(__half2& lo, __half2& hi, unsigned ua, unsigned ub) {
    const __half2 ha = *reinterpret_cast<const __half2*>(&ua);
    const __half2 hb = *reinterpret_cast<const __half2*>(&ub);
    lo = __lows2half2(ha, hb);
    hi = __highs2half2(ha, hb);
}

__global__ void __launch_bounds__(512) cnn_max(
    const int* __restrict__ word,
    const float* __restrict__ b2, const float* __restrict__ b3,
    const float* __restrict__ b4, const float* __restrict__ b5,
    const float* __restrict__ b6,
    float* __restrict__ out)
{
    __shared__ int sidx[32 * LSEQ];
    const int tid = threadIdx.x;

    sidx[tid]       = word[blockIdx.x * 1024 + tid];
    sidx[tid + 512] = word[blockIdx.x * 1024 + 512 + tid];
    __syncthreads();

    const int g  = tid >> 8;          // group: warps 0-7 -> A, 8-15 -> B
    const int wp = (tid >> 4) & 15;   // word-pair in block
    const int f  = tid & 15;          // filter
    const int* ma = &sidx[(2 * wp) * LSEQ];
    const int* mb = ma + LSEQ;

    const __half2 H2ZERO = __half2half2(__ushort_as_half((unsigned short)0));
    const __half2 H2NEG  = __half2half2(__ushort_as_half((unsigned short)0xFBFF));

    const char* __restrict__ tb =
        reinterpret_cast<const char*>(g_Th) + g * 512 + f * 16;
    float* oA = out + (blockIdx.x * 32 + 2 * wp) * 80;
    float* oB = oA + 80;

    if (g == 0) {
        // ---- group A: kernels {2,3,4}, taps 0..8, pads {0,0,1} ----
        const float bias[3] = {b2[f], b3[f], b4[f]};
        const int KK[3] = {2, 3, 4}, PP[3] = {0, 0, 1}, AB[3] = {0, 2, 5};

        __half2 acc[9];
#pragma unroll
        for (int i = 0; i < 9; ++i) acc[i] = H2ZERO;
        __half2 mx[3];
#pragma unroll
        for (int i = 0; i < 3; ++i) mx[i] = H2NEG;

#pragma unroll
        for (int pos = 0; pos < LSEQ; ++pos) {
            int va = ma[pos]; va = (va < 0) ? VOC : va;
            int vb = mb[pos]; vb = (vb < 0) ? VOC : vb;
            const char* pa = tb + va * 1024;
            const char* pb = tb + vb * 1024;
            const uint4    a0 = *reinterpret_cast<const uint4*>(pa);
            const unsigned a1 = *reinterpret_cast<const unsigned*>(pa + 256);
            const uint4    b0 = *reinterpret_cast<const uint4*>(pb);
            const unsigned b1 = *reinterpret_cast<const unsigned*>(pb + 256);

            __half2 w[9], dummy;
            pack2(w[0], w[1], a0.x, b0.x);
            pack2(w[2], w[3], a0.y, b0.y);
            pack2(w[4], w[5], a0.z, b0.z);
            pack2(w[6], w[7], a0.w, b0.w);
            pack2(w[8], dummy, a1, b1);
            (void)dummy;

#pragma unroll
            for (int i = 0; i < 3; ++i) {
                const int k = KK[i], p_ = PP[i], ab = AB[i];
                const int lout = LSEQ + 2 * p_ - k + 1;
                const int q = pos + p_;
#pragma unroll
                for (int j = 0; j < 4; ++j) {
                    if (j < k) {
                        const int t = q - j;
                        if (t >= 0 && t < lout)
                            acc[ab + (t % k)] = __hadd2(acc[ab + (t % k)], w[ab + j]);
                    }
                }
                const int tc = q - (k - 1);
                if (tc >= 0 && tc < lout) {
                    const int s = ab + (tc % k);
                    mx[i] = __hmax2(mx[i], acc[s]);
                    acc[s] = H2ZERO;
                }
            }
        }
        // epilogue: only k=4 (p=1) completes at pos 32
#pragma unroll
        for (int i = 0; i < 3; ++i) {
            const int k = KK[i], p_ = PP[i], ab = AB[i];
            const int lout = LSEQ + 2 * p_ - k + 1;
            const int tc = LSEQ + p_ - (k - 1);
            if (tc >= 0 && tc < lout)
                mx[i] = __hmax2(mx[i], acc[ab + (tc % k)]);
        }
#pragma unroll
        for (int i = 0; i < 3; ++i) {
            oA[i * 16 + f] = __half2float(__low2half(mx[i]))  + bias[i];
            oB[i * 16 + f] = __half2float(__high2half(mx[i])) + bias[i];
        }
    } else {
        // ---- group B: kernels {5,6}, taps 0..10, pads {2,3} ----
        const float bias[2] = {b5[f], b6[f]};
        const int KK[2] = {5, 6}, PP[2] = {2, 3}, AB[2] = {0, 5};

        __half2 acc[11];
#pragma unroll
        for (int i = 0; i < 11; ++i) acc[i] = H2ZERO;
        __half2 mx[2];
#pragma unroll
        for (int i = 0; i < 2; ++i) mx[i] = H2NEG;

#pragma unroll
        for (int pos = 0; pos < LSEQ; ++pos) {
            int va = ma[pos]; va = (va < 0) ? VOC : va;
            int vb = mb[pos]; vb = (vb < 0) ? VOC : vb;
            const char* pa = tb + va * 1024;
            const char* pb = tb + vb * 1024;
            const uint4 a0 = *reinterpret_cast<const uint4*>(pa);
            const uint2 a1 = *reinterpret_cast<const uint2*>(pa + 256);
            const uint4 b0 = *reinterpret_cast<const uint4*>(pb);
            const uint2 b1 = *reinterpret_cast<const uint2*>(pb + 256);

            __half2 w[11], dummy;
            pack2(w[0], w[1], a0.x, b0.x);
            pack2(w[2], w[3], a0.y, b0.y);
            pack2(w[4], w[5], a0.z, b0.z);
            pack2(w[6], w[7], a0.w, b0.w);
            pack2(w[8], w[9], a1.x, b1.x);
            pack2(w[10], dummy, a1.y, b1.y);
            (void)dummy;

#pragma unroll
            for (int i = 0; i < 2; ++i) {
                const int k = KK[i], p_ = PP[i], ab = AB[i];
                const int lout = LSEQ + 2 * p_ - k + 1;
                const int q = pos + p_;
#pragma unroll
                for (int j = 0; j < 6; ++j) {
                    if (j < k) {
                        const int t = q - j;
                        if (t >= 0 && t < lout)
                            acc[ab + (t % k)] = __hadd2(acc[ab + (t % k)], w[ab + j]);
                    }
                }
                const int tc = q - (k - 1);
                if (tc >= 0 && tc < lout) {
                    const int s = ab + (tc % k);
                    mx[i] = __hmax2(mx[i], acc[s]);
                    acc[s] = H2ZERO;
                }
            }
        }
        // epilogue: k5 (p=2) completes through pos 33, k6 (p=3) through pos 34
#pragma unroll
        for (int pos = LSEQ; pos <= LSEQ + 2; ++pos) {
#pragma unroll
            for (int i = 0; i < 2; ++i) {
                const int k = KK[i], p_ = PP[i], ab = AB[i];
                const int lout = LSEQ + 2 * p_ - k + 1;
                const int tc = pos + p_ - (k - 1);
                if (tc >= 0 && tc < lout)
                    mx[i] = __hmax2(mx[i], acc[ab + (tc % k)]);
            }
        }
#pragma unroll
        for (int i = 0; i < 2; ++i) {
            oA[48 + i * 16 + f] = __half2float(__low2half(mx[i]))  + bias[i];
            oB[48 + i * 16 + f] = __half2float(__high2half(mx[i])) + bias[i];
        }
    }
}

// ---------------------------------------------------------------------------
extern "C" void kernel_launch(void* const* d_in, const int* in_sizes, int n_in,
                              void* d_out, int out_size)
{
    const int*   word = (const int*)  d_in[0];
    const float* emb  = (const float*)d_in[1];
    const float* w2   = (const float*)d_in[2];
    const float* b2   = (const float*)d_in[3];
    const float* w3   = (const float*)d_in[4];
    const float* b3   = (const float*)d_in[5];
    const float* w4   = (const float*)d_in[6];
    const float* b4   = (const float*)d_in[7];
    const float* w5   = (const float*)d_in[8];
    const float* b5   = (const float*)d_in[9];
    const float* w6   = (const float*)d_in[10];
    const float* b6   = (const float*)d_in[11];
    float* out = (float*)d_out;

    const size_t smem_bytes = (size_t)(W_FLOATS + VT * EMB) * sizeof(float);  // ~166KB
    cudaFuncSetAttribute(build_table,
                         cudaFuncAttributeMaxDynamicSharedMemorySize,
                         (int)smem_bytes);

    build_table<<<VOC / VT, 320, smem_bytes>>>(emb, w2, w3, w4, w5, w6);
    cnn_max<<<512, 512>>>(word, b2, b3, b4, b5, b6, out);
}

// round 13
// speedup vs baseline: 1.1232x; 1.1232x over previous
#include <cuda_runtime.h>
#include <cuda_fp16.h>

// CNNEmbedding via vocab-factorized fp16 table, split-filter-bank edition.
// R13: table block packed to 768B/v with line-aligned chunk-1 regions
// (gA odd tap as ushort, gB tail taps as uint2) -> ~25% fewer L1 wavefronts
// in cnn_max. build_table reverted to R10 (VT=8, grid=64, direct strided).

#define VOC 512
#define EMB 128
#define NF 16
#define NPAIR 20
#define LSEQ 32
#define VT 8
#define BLK_HALVES 384    // per-v block: 768 bytes

__device__ __align__(16) __half g_Th[(VOC + 1) * BLK_HALVES];   // zero-init; row VOC = unk

// ---------------------------------------------------------------------------
// Kernel 1: build table. grid = VOC/VT = 64, block = 320 (16 f x 20 taps).
// Direct raw-weight reads (stride k), emb staged transposed in smem. (= R10)
// ---------------------------------------------------------------------------
__global__ void __launch_bounds__(320) build_table(
    const float* __restrict__ emb,
    const float* __restrict__ w2, const float* __restrict__ w3,
    const float* __restrict__ w4, const float* __restrict__ w5,
    const float* __restrict__ w6)
{
    __shared__ __align__(16) float semb[EMB][VT];   // 4 KB
    const int v0  = blockIdx.x * VT;
    const int tid = threadIdx.x;

    for (int i = tid; i < VT * EMB; i += 320) {
        const int t = i >> 7;          // i / 128
        const int e = i & 127;
        semb[e][t] = emb[v0 * EMB + i];
    }
    __syncthreads();

    const int f  = tid / NPAIR;
    const int pr = tid - f * NPAIR;

    int k, j;
    const float* w;
    if (pr < 2)       { k = 2; j = pr;      w = w2; }
    else if (pr < 5)  { k = 3; j = pr - 2;  w = w3; }
    else if (pr < 9)  { k = 4; j = pr - 5;  w = w4; }
    else if (pr < 14) { k = 5; j = pr - 9;  w = w5; }
    else              { k = 6; j = pr - 14; w = w6; }

    // w layout [O=16, I=128, K=k]: element (f, e, j) at w[f*128*k + e*k + j]
    const float* wrow = w + f * EMB * k + j;

    float acc[VT];
#pragma unroll
    for (int t = 0; t < VT; ++t) acc[t] = 0.f;

#pragma unroll 4
    for (int e = 0; e < EMB; ++e) {
        const float we = wrow[e * k];
        const float4 ev0 = *reinterpret_cast<const float4*>(&semb[e][0]);
        const float4 ev1 = *reinterpret_cast<const float4*>(&semb[e][4]);
        acc[0] = fmaf(ev0.x, we, acc[0]);
        acc[1] = fmaf(ev0.y, we, acc[1]);
        acc[2] = fmaf(ev0.z, we, acc[2]);
        acc[3] = fmaf(ev0.w, we, acc[3]);
        acc[4] = fmaf(ev1.x, we, acc[4]);
        acc[5] = fmaf(ev1.y, we, acc[5]);
        acc[6] = fmaf(ev1.z, we, acc[6]);
        acc[7] = fmaf(ev1.w, we, acc[7]);
    }

    // Packed 768B/v layout (half offsets within the 384-half block):
    //   gA c0 (slots 0..7):  f*8 + slot            bytes [0,256)
    //   gB c0 (slots 0..7):  128 + f*8 + slot      bytes [256,512)
    //   gA c1 (slot 8):      256 + f               bytes [512,544)
    //   gB c1 (slots 8..10): 320 + f*4 + (slot-8)  bytes [640,768) (4th half pad)
    const int g = (pr >= 9) ? 1 : 0;
    const int slot = pr - 9 * g;
    int off;
    if (g == 0) off = (slot < 8) ? (f * 8 + slot) : (256 + f);
    else        off = (slot < 8) ? (128 + f * 8 + slot) : (320 + f * 4 + (slot - 8));
#pragma unroll
    for (int t = 0; t < VT; ++t)
        g_Th[(v0 + t) * BLK_HALVES + off] = __float2half(acc[t]);
}

// ---------------------------------------------------------------------------
// Kernel 2: gather + fp16 dual-word sliding-window max.
// block = 512 = [g:2][wordpair:16][f:16]; grid = 512 (32 words per block).
// ---------------------------------------------------------------------------
__device__ __forceinline__ void pack2(__half2& lo, __half2& hi, unsigned ua, unsigned ub) {
    const __half2 ha = *reinterpret_cast<const __half2*>(&ua);
    const __half2 hb = *reinterpret_cast<const __half2*>(&ub);
    lo = __lows2half2(ha, hb);
    hi = __highs2half2(ha, hb);
}

__global__ void __launch_bounds__(512) cnn_max(
    const int* __restrict__ word,
    const float* __restrict__ b2, const float* __restrict__ b3,
    const float* __restrict__ b4, const float* __restrict__ b5,
    const float* __restrict__ b6,
    float* __restrict__ out)
{
    __shared__ int sidx[32 * LSEQ];
    const int tid = threadIdx.x;

    sidx[tid]       = word[blockIdx.x * 1024 + tid];
    sidx[tid + 512] = word[blockIdx.x * 1024 + 512 + tid];
    __syncthreads();

    const int g  = tid >> 8;          // group: warps 0-7 -> A, 8-15 -> B
    const int wp = (tid >> 4) & 15;   // word-pair in block
    const int f  = tid & 15;          // filter
    const int* ma = &sidx[(2 * wp) * LSEQ];
    const int* mb = ma + LSEQ;

    const __half2 H2ZERO = __half2half2(__ushort_as_half((unsigned short)0));
    const __half2 H2NEG  = __half2half2(__ushort_as_half((unsigned short)0xFBFF));

    const char* __restrict__ base = reinterpret_cast<const char*>(g_Th);
    float* oA = out + (blockIdx.x * 32 + 2 * wp) * 80;
    float* oB = oA + 80;

    if (g == 0) {
        // ---- group A: kernels {2,3,4}, taps 0..8, pads {0,0,1} ----
        const float bias[3] = {b2[f], b3[f], b4[f]};
        const int KK[3] = {2, 3, 4}, PP[3] = {0, 0, 1}, AB[3] = {0, 2, 5};

        __half2 acc[9];
#pragma unroll
        for (int i = 0; i < 9; ++i) acc[i] = H2ZERO;
        __half2 mx[3];
#pragma unroll
        for (int i = 0; i < 3; ++i) mx[i] = H2NEG;

#pragma unroll
        for (int pos = 0; pos < LSEQ; ++pos) {
            int va = ma[pos]; va = (va < 0) ? VOC : va;
            int vb = mb[pos]; vb = (vb < 0) ? VOC : vb;
            const char* pa = base + va * 768;
            const char* pb = base + vb * 768;
            const uint4 a0 = *reinterpret_cast<const uint4*>(pa + f * 16);
            const uint4 b0 = *reinterpret_cast<const uint4*>(pb + f * 16);
            const unsigned short a1 = *reinterpret_cast<const unsigned short*>(pa + 512 + f * 2);
            const unsigned short b1 = *reinterpret_cast<const unsigned short*>(pb + 512 + f * 2);

            __half2 w[9];
            pack2(w[0], w[1], a0.x, b0.x);
            pack2(w[2], w[3], a0.y, b0.y);
            pack2(w[4], w[5], a0.z, b0.z);
            pack2(w[6], w[7], a0.w, b0.w);
            const unsigned u8 = (unsigned)a1 | ((unsigned)b1 << 16);
            w[8] = *reinterpret_cast<const __half2*>(&u8);

#pragma unroll
            for (int i = 0; i < 3; ++i) {
                const int k = KK[i], p_ = PP[i], ab = AB[i];
                const int lout = LSEQ + 2 * p_ - k + 1;
                const int q = pos + p_;
#pragma unroll
                for (int j = 0; j < 4; ++j) {
                    if (j < k) {
                        const int t = q - j;
                        if (t >= 0 && t < lout)
                            acc[ab + (t % k)] = __hadd2(acc[ab + (t % k)], w[ab + j]);
                    }
                }
                const int tc = q - (k - 1);
                if (tc >= 0 && tc < lout) {
                    const int s = ab + (tc % k);
                    mx[i] = __hmax2(mx[i], acc[s]);
                    acc[s] = H2ZERO;
                }
            }
        }
        // epilogue: only k=4 (p=1) completes at pos 32
#pragma unroll
        for (int i = 0; i < 3; ++i) {
            const int k = KK[i], p_ = PP[i], ab = AB[i];
            const int lout = LSEQ + 2 * p_ - k + 1;
            const int tc = LSEQ + p_ - (k - 1);
            if (tc >= 0 && tc < lout)
                mx[i] = __hmax2(mx[i], acc[ab + (tc % k)]);
        }
#pragma unroll
        for (int i = 0; i < 3; ++i) {
            oA[i * 16 + f] = __half2float(__low2half(mx[i]))  + bias[i];
            oB[i * 16 + f] = __half2float(__high2half(mx[i])) + bias[i];
        }
    } else {
        // ---- group B: kernels {5,6}, taps 0..10, pads {2,3} ----
        const float bias[2] = {b5[f], b6[f]};
        const int KK[2] = {5, 6}, PP[2] = {2, 3}, AB[2] = {0, 5};

        __half2 acc[11];
#pragma unroll
        for (int i = 0; i < 11; ++i) acc[i] = H2ZERO;
        __half2 mx[2];
#pragma unroll
        for (int i = 0; i < 2; ++i) mx[i] = H2NEG;

#pragma unroll
        for (int pos = 0; pos < LSEQ; ++pos) {
            int va = ma[pos]; va = (va < 0) ? VOC : va;
            int vb = mb[pos]; vb = (vb < 0) ? VOC : vb;
            const char* pa = base + va * 768;
            const char* pb = base + vb * 768;
            const uint4 a0 = *reinterpret_cast<const uint4*>(pa + 256 + f * 16);
            const uint4 b0 = *reinterpret_cast<const uint4*>(pb + 256 + f * 16);
            const uint2 a1 = *reinterpret_cast<const uint2*>(pa + 640 + f * 8);
            const uint2 b1 = *reinterpret_cast<const uint2*>(pb + 640 + f * 8);

            __half2 w[11], dummy;
            pack2(w[0], w[1], a0.x, b0.x);
            pack2(w[2], w[3], a0.y, b0.y);
            pack2(w[4], w[5], a0.z, b0.z);
            pack2(w[6], w[7], a0.w, b0.w);
            pack2(w[8], w[9], a1.x, b1.x);
            pack2(w[10], dummy, a1.y, b1.y);
            (void)dummy;

#pragma unroll
            for (int i = 0; i < 2; ++i) {
                const int k = KK[i], p_ = PP[i], ab = AB[i];
                const int lout = LSEQ + 2 * p_ - k + 1;
                const int q = pos + p_;
#pragma unroll
                for (int j = 0; j < 6; ++j) {
                    if (j < k) {
                        const int t = q - j;
                        if (t >= 0 && t < lout)
                            acc[ab + (t % k)] = __hadd2(acc[ab + (t % k)], w[ab + j]);
                    }
                }
                const int tc = q - (k - 1);
                if (tc >= 0 && tc < lout) {
                    const int s = ab + (tc % k);
                    mx[i] = __hmax2(mx[i], acc[s]);
                    acc[s] = H2ZERO;
                }
            }
        }
        // epilogue: k5 (p=2) completes through pos 33, k6 (p=3) through pos 34
#pragma unroll
        for (int pos = LSEQ; pos <= LSEQ + 2; ++pos) {
#pragma unroll
            for (int i = 0; i < 2; ++i) {
                const int k = KK[i], p_ = PP[i], ab = AB[i];
                const int lout = LSEQ + 2 * p_ - k + 1;
                const int tc = pos + p_ - (k - 1);
                if (tc >= 0 && tc < lout)
                    mx[i] = __hmax2(mx[i], acc[ab + (tc % k)]);
            }
        }
#pragma unroll
        for (int i = 0; i < 2; ++i) {
            oA[48 + i * 16 + f] = __half2float(__low2half(mx[i]))  + bias[i];
            oB[48 + i * 16 + f] = __half2float(__high2half(mx[i])) + bias[i];
        }
    }
}

// ---------------------------------------------------------------------------
extern "C" void kernel_launch(void* const* d_in, const int* in_sizes, int n_in,
                              void* d_out, int out_size)
{
    const int*   word = (const int*)  d_in[0];
    const float* emb  = (const float*)d_in[1];
    const float* w2   = (const float*)d_in[2];
    const float* b2   = (const float*)d_in[3];
    const float* w3   = (const float*)d_in[4];
    const float* b3   = (const float*)d_in[5];
    const float* w4   = (const float*)d_in[6];
    const float* b4   = (const float*)d_in[7];
    const float* w5   = (const float*)d_in[8];
    const float* b5   = (const float*)d_in[9];
    const float* w6   = (const float*)d_in[10];
    const float* b6   = (const float*)d_in[11];
    float* out = (float*)d_out;

    build_table<<<VOC / VT, 320>>>(emb, w2, w3, w4, w5, w6);
    cnn_max<<<512, 512>>>(word, b2, b3, b4, b5, b6, out);
}